// round 2
// baseline (speedup 1.0000x reference)
#include <cuda_runtime.h>
#include <cuda_bf16.h>
#include <mma.h>
#include <math.h>

using namespace nvcuda;

// Problem constants
#define N_ROWS 4096
#define D_DIM  2048
#define V_DIM  32000
#define SOFTCAP_F 30.0f
#define INV_SOFTCAP (1.0f/30.0f)
#define LS 0.1f

// Scratch (allocation-free: __device__ globals)
__device__ float g_logits[(size_t)N_ROWS * V_DIM];   // 512 MB
__device__ float g_row[N_ROWS];
__device__ int   g_valid[N_ROWS];

// ---------------- GEMM: C = A[4096,2048] * B[2048,32000], TF32 wmma ----------------
#define BM 128
#define BN 128
#define BK 32
#define APAD 4
#define BPAD 4

__global__ __launch_bounds__(256) void gemm_tf32(const float* __restrict__ A,
                                                 const float* __restrict__ B) {
    __shared__ float As[BM][BK + APAD];
    __shared__ float Bs[BK][BN + BPAD];

    const int tid  = threadIdx.x;
    const int warp = tid >> 5;
    const int wm   = warp >> 1;  // 0..3 -> 32-row strip
    const int wn   = warp & 1;   // 0..1 -> 64-col strip
    const int rowBase = blockIdx.y * BM;
    const int colBase = blockIdx.x * BN;

    wmma::fragment<wmma::accumulator, 16, 16, 8, float> acc[2][4];
    #pragma unroll
    for (int i = 0; i < 2; i++)
        #pragma unroll
        for (int j = 0; j < 4; j++)
            wmma::fill_fragment(acc[i][j], 0.0f);

    for (int k0 = 0; k0 < D_DIM; k0 += BK) {
        // Load A tile 128x32 (float4)
        #pragma unroll
        for (int i = tid; i < BM * BK / 4; i += 256) {
            int r  = i >> 3;
            int c4 = i & 7;
            float4 v = *reinterpret_cast<const float4*>(
                A + (size_t)(rowBase + r) * D_DIM + k0 + c4 * 4);
            *reinterpret_cast<float4*>(&As[r][c4 * 4]) = v;
        }
        // Load B tile 32x128 (float4)
        #pragma unroll
        for (int i = tid; i < BK * BN / 4; i += 256) {
            int kr = i >> 5;
            int c4 = i & 31;
            float4 v = *reinterpret_cast<const float4*>(
                B + (size_t)(k0 + kr) * V_DIM + colBase + c4 * 4);
            *reinterpret_cast<float4*>(&Bs[kr][c4 * 4]) = v;
        }
        __syncthreads();

        #pragma unroll
        for (int ks = 0; ks < BK / 8; ks++) {
            wmma::fragment<wmma::matrix_a, 16, 16, 8, wmma::precision::tf32, wmma::row_major> a_frag[2];
            wmma::fragment<wmma::matrix_b, 16, 16, 8, wmma::precision::tf32, wmma::row_major> b_frag[4];
            #pragma unroll
            for (int i = 0; i < 2; i++) {
                wmma::load_matrix_sync(a_frag[i], &As[wm * 32 + i * 16][ks * 8], BK + APAD);
                #pragma unroll
                for (int t = 0; t < a_frag[i].num_elements; t++)
                    a_frag[i].x[t] = wmma::__float_to_tf32(a_frag[i].x[t]);
            }
            #pragma unroll
            for (int j = 0; j < 4; j++) {
                wmma::load_matrix_sync(b_frag[j], &Bs[ks * 8][wn * 64 + j * 16], BN + BPAD);
                #pragma unroll
                for (int t = 0; t < b_frag[j].num_elements; t++)
                    b_frag[j].x[t] = wmma::__float_to_tf32(b_frag[j].x[t]);
            }
            #pragma unroll
            for (int i = 0; i < 2; i++)
                #pragma unroll
                for (int j = 0; j < 4; j++)
                    wmma::mma_sync(acc[i][j], a_frag[i], b_frag[j], acc[i][j]);
        }
        __syncthreads();
    }

    #pragma unroll
    for (int i = 0; i < 2; i++)
        #pragma unroll
        for (int j = 0; j < 4; j++) {
            size_t off = (size_t)(rowBase + wm * 32 + i * 16) * V_DIM
                       + colBase + wn * 64 + j * 16;
            wmma::store_matrix_sync(g_logits + off, acc[i][j], V_DIM, wmma::mem_row_major);
        }
}

// ---------------- Per-row: softcap + online LSE + sums ----------------
// NOTE: targets is int32. JAX defaults to 32-bit ints (jax_enable_x64 off), so
// randint(..., dtype=jnp.int64) materializes as int32. Reading int64 here was
// the R0 illegal-access bug (fused pairs of int32 -> wild index into g_logits).
__global__ __launch_bounds__(256) void row_reduce(const int* __restrict__ targets) {
    const int row = blockIdx.x;
    const float* lp = g_logits + (size_t)row * V_DIM;
    const int tid = threadIdx.x;

    float m = -INFINITY, s = 0.0f, sumz = 0.0f;
    for (int v = tid; v < V_DIM; v += 256) {
        float z = SOFTCAP_F * tanhf(lp[v] * INV_SOFTCAP);
        sumz += z;
        if (z > m) { s = s * expf(m - z) + 1.0f; m = z; }
        else       { s += expf(z - m); }
    }

    __shared__ float sm[256], ss[256], sz[256];
    sm[tid] = m; ss[tid] = s; sz[tid] = sumz;
    __syncthreads();
    for (int off = 128; off > 0; off >>= 1) {
        if (tid < off) {
            float m1 = sm[tid], s1 = ss[tid];
            float m2 = sm[tid + off], s2 = ss[tid + off];
            float M = fmaxf(m1, m2);
            sm[tid] = M;
            ss[tid] = s1 * expf(m1 - M) + s2 * expf(m2 - M);
            sz[tid] += sz[tid + off];
        }
        __syncthreads();
    }

    if (tid == 0) {
        float lse = sm[0] + logf(ss[0]);
        int t = targets[row];
        int valid = (t != -100);
        // Defensive clamp: a bounded-but-wrong read shows up as rel_err
        // (diagnosable); an OOB read is an illegal access (not).
        int ts = (t >= 0 && t < V_DIM) ? t : 0;
        float zt = SOFTCAP_F * tanhf(lp[ts] * INV_SOFTCAP);
        float nll    = lse - zt;
        float smooth = lse - sz[0] / (float)V_DIM;
        float ce     = (1.0f - LS) * nll + LS * smooth;
        g_row[row]   = valid ? (ce + 1e-4f * lse * lse) : 0.0f;
        g_valid[row] = valid;
    }
}

// ---------------- Final scalar reduction ----------------
__global__ __launch_bounds__(1024) void final_reduce(float* __restrict__ out) {
    const int tid = threadIdx.x;
    float s = 0.0f; int c = 0;
    for (int i = tid; i < N_ROWS; i += 1024) { s += g_row[i]; c += g_valid[i]; }
    __shared__ float sf[1024];
    __shared__ int   si[1024];
    sf[tid] = s; si[tid] = c;
    __syncthreads();
    for (int off = 512; off > 0; off >>= 1) {
        if (tid < off) { sf[tid] += sf[tid + off]; si[tid] += si[tid + off]; }
        __syncthreads();
    }
    if (tid == 0) out[0] = sf[0] / (float)si[0];
}

extern "C" void kernel_launch(void* const* d_in, const int* in_sizes, int n_in,
                              void* d_out, int out_size) {
    const float* A       = (const float*)d_in[0];   // input  [4096, 2048]
    const float* B       = (const float*)d_in[1];   // weight [2048, 32000]
    const int*   targets = (const int*)d_in[2];     // [4096] int32 (JAX x64 disabled)
    // d_in[3] = bias scalar (0) -> reference skips the bias branch; ignore.

    dim3 grid(V_DIM / BN, N_ROWS / BM);   // 250 x 32
    gemm_tf32<<<grid, 256>>>(A, B);
    row_reduce<<<N_ROWS, 256>>>(targets);
    final_reduce<<<1, 1024>>>((float*)d_out);
}

// round 4
// speedup vs baseline: 1.7731x; 1.7731x over previous
#include <cuda_runtime.h>
#include <cuda_bf16.h>
#include <cuda_fp16.h>
#include <cstdint>
#include <math.h>

// ---------------- Problem constants ----------------
#define N_ROWS 4096
#define D_DIM  2048
#define V_DIM  32000

#define BM 128
#define BN 128
#define BK 32
#define KCHUNKS (D_DIM / BK)   // 64
#define MT (N_ROWS / BM)       // 32
#define NT (V_DIM / BN)        // 250
#define S  4                   // pipeline stages

#define ROWB   80              // padded smem row stride (64B data + 16B pad)
#define TILEB  (128 * ROWB)    // 10240 per operand tile
#define STAGEB (2 * TILEB)     // 20480
#define DYNS   (S * STAGEB)    // 81920

#define C30LOG2E 43.28085123f  // 30 * log2(e)

// ---------------- Scratch (__device__ globals; no allocs) ----------------
__device__ __align__(16) __nv_bfloat16 g_A16[(size_t)N_ROWS * D_DIM];  // 16 MB
__device__ __align__(16) __nv_bfloat16 g_B16t[(size_t)V_DIM * D_DIM];  // 131 MB (B^T, k-contiguous)
__device__ float g_sumexp[N_ROWS];   // sum exp(z - 30)
__device__ float g_sumt[N_ROWS];     // sum tanh(d/30)  (sumz = 30 * sumt)
__device__ float g_zt[N_ROWS];       // z at target column

// ---------------- small asm helpers (baseline ISA only) ----------------
__device__ __forceinline__ uint32_t smem_u32(const void* p) {
    uint32_t a;
    asm("{ .reg .u64 t; cvta.to.shared.u64 t, %1; cvt.u32.u64 %0, t; }" : "=r"(a) : "l"(p));
    return a;
}
__device__ __forceinline__ void cp16(uint32_t dst, const void* src) {
    asm volatile("cp.async.cg.shared.global [%0], [%1], 16;" :: "r"(dst), "l"(src) : "memory");
}
__device__ __forceinline__ void ldm4(uint32_t* r, uint32_t addr) {
    asm volatile("ldmatrix.sync.aligned.m8n8.x4.shared.b16 {%0,%1,%2,%3}, [%4];"
                 : "=r"(r[0]), "=r"(r[1]), "=r"(r[2]), "=r"(r[3]) : "r"(addr));
}
__device__ __forceinline__ void mma16816(float* c, const uint32_t* a, const uint32_t* b) {
    asm volatile("mma.sync.aligned.m16n8k16.row.col.f32.bf16.bf16.f32 "
                 "{%0,%1,%2,%3},{%4,%5,%6,%7},{%8,%9},{%0,%1,%2,%3};"
                 : "+f"(c[0]), "+f"(c[1]), "+f"(c[2]), "+f"(c[3])
                 : "r"(a[0]), "r"(a[1]), "r"(a[2]), "r"(a[3]), "r"(b[0]), "r"(b[1]));
}
__device__ __forceinline__ float ex2f(float x) {
    float y; asm("ex2.approx.f32 %0, %1;" : "=f"(y) : "f"(x)); return y;
}
__device__ __forceinline__ float tanhf_fast(float x) {
    float y; asm("tanh.approx.f32 %0, %1;" : "=f"(y) : "f"(x)); return y;
}
__device__ __forceinline__ __half2 tanh2(__half2 x) {
    uint32_t xi = *(uint32_t*)&x, y;
    asm("tanh.approx.f16x2 %0, %1;" : "=r"(y) : "r"(xi));
    return *(__half2*)&y;
}

// ---------------- Init ----------------
__global__ void init_acc() {
    int i = blockIdx.x * blockDim.x + threadIdx.x;
    if (i < N_ROWS) { g_sumexp[i] = 0.0f; g_sumt[i] = 0.0f; g_zt[i] = 0.0f; }
}

// ---------------- Prepass A: fp32 -> bf16, row-major ----------------
__global__ __launch_bounds__(256) void conv_a(const float* __restrict__ A) {
    size_t i = ((size_t)blockIdx.x * 256 + threadIdx.x) * 8;
    float4 f0 = *reinterpret_cast<const float4*>(A + i);
    float4 f1 = *reinterpret_cast<const float4*>(A + i + 4);
    __nv_bfloat162 b0 = __floats2bfloat162_rn(f0.x, f0.y);
    __nv_bfloat162 b1 = __floats2bfloat162_rn(f0.z, f0.w);
    __nv_bfloat162 b2 = __floats2bfloat162_rn(f1.x, f1.y);
    __nv_bfloat162 b3 = __floats2bfloat162_rn(f1.z, f1.w);
    *reinterpret_cast<uint4*>(g_A16 + i) =
        make_uint4(*(uint32_t*)&b0, *(uint32_t*)&b1, *(uint32_t*)&b2, *(uint32_t*)&b3);
}

// ---------------- Prepass B: fp32 [2048,32000] -> bf16 B^T [32000,2048] ----------------
__global__ __launch_bounds__(256) void conv_bt(const float* __restrict__ B) {
    __shared__ float sT[32][257];
    const int nb = blockIdx.x;   // 125 blocks of 256 n
    const int kb = blockIdx.y;   // 64 blocks of 32 k
    const int tid = threadIdx.x;
    #pragma unroll
    for (int k = 0; k < 32; k++)
        sT[k][tid] = B[(size_t)(kb * 32 + k) * V_DIM + nb * 256 + tid];
    __syncthreads();
    __nv_bfloat16* dst = g_B16t + (size_t)(nb * 256 + tid) * D_DIM + kb * 32;
    uint32_t pk[16];
    #pragma unroll
    for (int j = 0; j < 16; j++) {
        __nv_bfloat162 p = __floats2bfloat162_rn(sT[2 * j][tid], sT[2 * j + 1][tid]);
        pk[j] = *(uint32_t*)&p;
    }
    #pragma unroll
    for (int q = 0; q < 4; q++)
        *reinterpret_cast<uint4*>(dst + q * 8) =
            make_uint4(pk[4 * q], pk[4 * q + 1], pk[4 * q + 2], pk[4 * q + 3]);
}

// ---------------- Fused GEMM (mma.sync bf16) + CE epilogue ----------------
__global__ __launch_bounds__(256, 2) void gemm_ce(const int* __restrict__ targets) {
    extern __shared__ char smraw[];
    const uint32_t base = smem_u32(smraw);
    const int tid = threadIdx.x, lane = tid & 31, wid = tid >> 5;
    const int wm = wid & 1, wn = wid >> 1;           // warp grid 2 (M) x 4 (N)
    const int mt = blockIdx.x, nt = blockIdx.y;

    // Per-thread cp.async sources: 2 chunks A + 2 chunks B, each 16B, advancing 64B/k-chunk
    const int rA = tid >> 2, cA = tid & 3;           // row 0..63 (+64 for second), 16B-chunk 0..3
    const char* srcA0 = (const char*)g_A16 + 2 * ((size_t)(mt * BM + rA) * D_DIM) + cA * 16;
    const char* srcA1 = srcA0 + 2 * (size_t)64 * D_DIM;
    const char* srcB0 = (const char*)g_B16t + 2 * ((size_t)(nt * BN + rA) * D_DIM) + cA * 16;
    const char* srcB1 = srcB0 + 2 * (size_t)64 * D_DIM;
    const uint32_t dA0 = rA * ROWB + cA * 16, dA1 = dA0 + 64 * ROWB;

    float acc[4][4][4];
    #pragma unroll
    for (int mi = 0; mi < 4; mi++)
        #pragma unroll
        for (int ni = 0; ni < 4; ni++)
            #pragma unroll
            for (int e = 0; e < 4; e++) acc[mi][ni][e] = 0.0f;

    // ldmatrix lane addressing (precomputed offsets within a tile)
    const uint32_t aOff = (wm * 64 + (lane & 15)) * ROWB + (lane >> 4) * 16;
    const uint32_t bOff = (wn * 32 + ((lane >> 4) << 3) + (lane & 7)) * ROWB + ((lane >> 3) & 1) * 16;

    // Prologue: prefetch S chunks
    #pragma unroll
    for (int s = 0; s < S; s++) {
        uint32_t sb = base + s * STAGEB;
        size_t ko = (size_t)s * 64;
        cp16(sb + dA0, srcA0 + ko);          cp16(sb + dA1, srcA1 + ko);
        cp16(sb + TILEB + dA0, srcB0 + ko);  cp16(sb + TILEB + dA1, srcB1 + ko);
        asm volatile("cp.async.commit_group;" ::: "memory");
    }

    for (int c = 0; c < KCHUNKS; c++) {
        asm volatile("cp.async.wait_group %0;" :: "n"(S - 1) : "memory");
        __syncthreads();
        const uint32_t Ab = base + (c & (S - 1)) * STAGEB;
        const uint32_t Bb = Ab + TILEB;
        #pragma unroll
        for (int kk = 0; kk < 2; kk++) {
            uint32_t a[4][4], b[4][2];
            #pragma unroll
            for (int p = 0; p < 2; p++) {    // B: two x4 loads -> frags for ni=2p, 2p+1
                uint32_t r[4];
                ldm4(r, Bb + bOff + p * 16 * ROWB + kk * 32);
                b[2 * p][0] = r[0]; b[2 * p][1] = r[1];
                b[2 * p + 1][0] = r[2]; b[2 * p + 1][1] = r[3];
            }
            #pragma unroll
            for (int mi = 0; mi < 4; mi++)
                ldm4(a[mi], Ab + aOff + mi * 16 * ROWB + kk * 32);
            #pragma unroll
            for (int mi = 0; mi < 4; mi++)
                #pragma unroll
                for (int ni = 0; ni < 4; ni++)
                    mma16816(acc[mi][ni], a[mi], b[ni]);
        }
        __syncthreads();
        const int pf = c + S;
        if (pf < KCHUNKS) {
            uint32_t sb = base + (c & (S - 1)) * STAGEB;
            size_t ko = (size_t)pf * 64;
            cp16(sb + dA0, srcA0 + ko);          cp16(sb + dA1, srcA1 + ko);
            cp16(sb + TILEB + dA0, srcB0 + ko);  cp16(sb + TILEB + dA1, srcB1 + ko);
        }
        asm volatile("cp.async.commit_group;" ::: "memory");
    }

    // ---- Fused CE epilogue on register accumulators ----
    // acc[mi][ni][{0,1}] -> row g, cols 2t,2t+1 ; acc[mi][ni][{2,3}] -> row g+8
    const __half2 inv30 = __float2half2_rn(1.0f / 30.0f);
    const int colBase = nt * BN + wn * 32;
    #pragma unroll
    for (int mi = 0; mi < 4; mi++) {
        #pragma unroll
        for (int rh = 0; rh < 2; rh++) {
            float se = 0.0f;
            __half2 st2 = __float2half2_rn(0.0f);
            #pragma unroll
            for (int ni = 0; ni < 4; ni++) {
                float d0 = acc[mi][ni][rh * 2 + 0];
                float d1 = acc[mi][ni][rh * 2 + 1];
                __half2 h = __floats2half2_rn(d0, d1);
                __half2 t2 = tanh2(__hmul2(h, inv30));
                st2 = __hadd2(st2, t2);
                float t0 = __low2float(t2), t1 = __high2float(t2);
                se += ex2f(fmaf(t0, C30LOG2E, -C30LOG2E));   // exp(z-30), z = 30*t
                se += ex2f(fmaf(t1, C30LOG2E, -C30LOG2E));
            }
            float st = __low2float(st2) + __high2float(st2);
            se += __shfl_xor_sync(0xffffffffu, se, 1);
            se += __shfl_xor_sync(0xffffffffu, se, 2);
            st += __shfl_xor_sync(0xffffffffu, st, 1);
            st += __shfl_xor_sync(0xffffffffu, st, 2);
            const int row = mt * BM + wm * 64 + mi * 16 + rh * 8 + (lane >> 2);
            if ((lane & 3) == 0) {
                atomicAdd(&g_sumexp[row], se);
                atomicAdd(&g_sumt[row], st);
            }
            // Target logit: unique owning thread in the grid (index arithmetic, no hot-loop compare)
            const int rel = targets[row] - colBase;
            if (rel >= 0 && rel < 32 && ((rel >> 1) & 3) == (lane & 3)) {
                float d = acc[mi][rel >> 3][rh * 2 + (rel & 1)];
                g_zt[row] = 30.0f * tanhf_fast(d * (1.0f / 30.0f));
            }
        }
    }
}

// ---------------- Final: per-row loss + scalar reduce ----------------
__global__ __launch_bounds__(1024) void final_reduce(const int* __restrict__ targets,
                                                     float* __restrict__ out) {
    const int tid = threadIdx.x;
    float s = 0.0f; int cnt = 0;
    for (int i = tid; i < N_ROWS; i += 1024) {
        float lse = 30.0f + logf(g_sumexp[i]);
        bool valid = (targets[i] != -100);
        float nll = lse - g_zt[i];
        float smooth = lse - 30.0f * g_sumt[i] * (1.0f / (float)V_DIM);
        float ce = 0.9f * nll + 0.1f * smooth;
        if (valid) { s += ce + 1e-4f * lse * lse; cnt++; }
    }
    __shared__ float sf[1024];
    __shared__ int   si[1024];
    sf[tid] = s; si[tid] = cnt;
    __syncthreads();
    for (int off = 512; off > 0; off >>= 1) {
        if (tid < off) { sf[tid] += sf[tid + off]; si[tid] += si[tid + off]; }
        __syncthreads();
    }
    if (tid == 0) out[0] = sf[0] / (float)si[0];
}

// ---------------- Host launch ----------------
extern "C" void kernel_launch(void* const* d_in, const int* in_sizes, int n_in,
                              void* d_out, int out_size) {
    const float* A       = (const float*)d_in[0];   // [4096, 2048]
    const float* B       = (const float*)d_in[1];   // [2048, 32000]
    const int*   targets = (const int*)d_in[2];     // [4096] int32
    // d_in[3] = bias (0) -> reference skips the bias branch

    cudaFuncSetAttribute(gemm_ce, cudaFuncAttributeMaxDynamicSharedMemorySize, DYNS);

    init_acc<<<16, 256>>>();
    conv_a<<<(N_ROWS * D_DIM) / (256 * 8), 256>>>(A);
    conv_bt<<<dim3(V_DIM / 256, D_DIM / 32), 256>>>(B);
    gemm_ce<<<dim3(MT, NT), 256, DYNS>>>(targets);
    final_reduce<<<1, 1024>>>(targets, (float*)d_out);
}